// round 13
// baseline (speedup 1.0000x reference)
#include <cuda_runtime.h>
#include <cuda_bf16.h>
#include <stdint.h>

// ---------------- problem constants ----------------
#define BB   128
#define CCH  8
#define HH   512
#define WW   32
#define KFLAT 131072
#define TT   4
#define NN   512
#define OO   16
#define RR   512

#define OUT_OFF  ((size_t)0)
#define CONV_OFF ((size_t)2048)
#define IN_OFF   ((size_t)67110912)
#define HID_OFF  ((size_t)67373056)

// ---------------- z1 work decomposition ----------------
#define NSLAB 64                         // K-slabs of 2048
#define SLABK (KFLAT / NSLAB)            // 2048
#define NUNIT (16 * NSLAB)               // 16 MN-tiles x 64 slabs = 1024
#define NCTA  148

// ---------------- scratch ----------------
__device__ __nv_bfloat16 g_S[(size_t)RR * KFLAT];     // spikes {0,1} bf16
__device__ float g_z1p[(size_t)NSLAB * RR * NN];      // per-slab partials (67MB)
__device__ float g_s1[RR * NN];
__device__ float g_z2[RR * NN];
__device__ float g_mean[BB * NN];

// packed f32x2 helpers
__device__ __forceinline__ unsigned long long pk2(float lo, float hi) {
    unsigned long long r;
    asm("mov.b64 %0, {%1, %2};" : "=l"(r) : "f"(lo), "f"(hi));
    return r;
}
__device__ __forceinline__ void upk2(float& lo, float& hi, unsigned long long v) {
    asm("mov.b64 {%0, %1}, %2;" : "=f"(lo), "=f"(hi) : "l"(v));
}
__device__ __forceinline__ void fma2(unsigned long long& d, unsigned long long a,
                                     unsigned long long b) {
    asm("fma.rn.f32x2 %0, %1, %2, %0;" : "+l"(d) : "l"(a), "l"(b));
}

// ---------------- kernel A: conv 3x3 SAME + 4-step LIF ----------------
__global__ void __launch_bounds__(256) conv_lif_kernel(const float* __restrict__ x,
                                                       const float* __restrict__ wc,
                                                       float* __restrict__ out)
{
    __shared__ float s_wc[144];
    int tid = threadIdx.x;
    if (tid < 144) s_wc[tid] = wc[tid];
    __syncthreads();

    int j    = tid & 31;
    int isub = tid >> 5;
    int blk  = blockIdx.x;
    int b    = blk >> 6;
    int i    = ((blk & 63) << 3) + isub;

    float xv[2][3][3];
#pragma unroll
    for (int c = 0; c < 2; c++) {
        const float* xb = x + (size_t)(b * 2 + c) * (HH * WW);
#pragma unroll
        for (int di = 0; di < 3; di++) {
            int ii = i + di - 1;
            bool iok = ((unsigned)ii < (unsigned)HH);
#pragma unroll
            for (int dj = 0; dj < 3; dj++) {
                int jj = j + dj - 1;
                bool ok = iok && ((unsigned)jj < (unsigned)WW);
                xv[c][di][dj] = ok ? xb[ii * WW + jj] : 0.0f;
            }
        }
    }

    int pix = i * WW + j;
#pragma unroll
    for (int o = 0; o < CCH; o++) {
        float acc = 0.0f;
#pragma unroll
        for (int c = 0; c < 2; c++)
#pragma unroll
            for (int di = 0; di < 3; di++)
#pragma unroll
                for (int dj = 0; dj < 3; dj++)
                    acc = fmaf(xv[c][di][dj], s_wc[o * 18 + c * 9 + di * 3 + dj], acc);

        float v = 0.0f;
        int kidx = o * (HH * WW) + pix;
#pragma unroll
        for (int t = 0; t < TT; t++) {
            v = 0.5f * v + acc;
            float s = (v >= 1.0f) ? 1.0f : 0.0f;
            v = (v >= 1.0f) ? 0.0f : v;
            out[CONV_OFF + (size_t)((b * TT + t) * CCH + o) * (HH * WW) + pix] = s;
            g_S[(size_t)(t * BB + b) * KFLAT + kidx] = __float2bfloat16(s);
        }
    }
}

// -------- kernel B: z1 = S @ w1^T, persistent f32x2 GEMM --------------------
// 148 persistent CTAs; unit = (128x128 tile, 2048-K slab); 1024 units RR-robin.
// BK=32, double-buffered dynamic smem, 1 syncthreads/iter. Deterministic.
#define SAF 132                    // float stride (16B-aligned rows)
#define Z1_SMEM (2 * 2 * 32 * SAF * 4)   // 67584 B

__global__ void __launch_bounds__(256) z1f2(const float* __restrict__ w1)
{
    extern __shared__ float smem[];

    const int tid = threadIdx.x;
    const int ty = tid >> 4, tx = tid & 15;
    const int m  = tid >> 1;               // staging row 0..127
    const int kh = (tid & 1) * 16;         // staging k-half

    for (int u = blockIdx.x; u < NUNIT; u += NCTA) {
        const int tile = u >> 6;           // 0..15
        const int slab = u & (NSLAB - 1);  // 0..63
        const int bm = tile >> 2, bn = tile & 3;
        const size_t k0 = (size_t)slab * SLABK;

        const __nv_bfloat16* gA = g_S + (size_t)(bm * 128 + m) * KFLAT + k0 + kh;
        const float*         gB = w1  + (size_t)(bn * 128 + m) * KFLAT + k0 + kh;

        unsigned long long acc2[8][4];
#pragma unroll
        for (int a = 0; a < 8; a++)
#pragma unroll
            for (int b = 0; b < 4; b++) acc2[a][b] = 0ULL;

        uint4  rA0, rA1;                   // 16 bf16
        float4 rB[4];                      // 16 fp32
        rA0 = ((const uint4*)gA)[0];
        rA1 = ((const uint4*)gA)[1];
#pragma unroll
        for (int i = 0; i < 4; i++) rB[i] = ((const float4*)gB)[i];

        const int nIter = SLABK / 32;      // 64
        for (int kt = 0; kt < nIter; kt++) {
            float* SA = smem + (kt & 1) * (2 * 32 * SAF);
            float* SB = SA + 32 * SAF;

            // ---- store staged slab (transposed; A cvt bf16->fp32) ----
            {
                const __nv_bfloat16* ah0 = (const __nv_bfloat16*)&rA0;
                const __nv_bfloat16* ah1 = (const __nv_bfloat16*)&rA1;
                const float* fb = (const float*)rB;
#pragma unroll
                for (int q = 0; q < 8; q++) {
                    SA[(kh + q) * SAF + m]     = __bfloat162float(ah0[q]);
                    SA[(kh + 8 + q) * SAF + m] = __bfloat162float(ah1[q]);
                }
#pragma unroll
                for (int q = 0; q < 16; q++)
                    SB[(kh + q) * SAF + m] = fb[q];
            }
            __syncthreads();

            // ---- prefetch next slab ----
            if (kt + 1 < nIter) {
                const size_t off = (size_t)(kt + 1) * 32;
                rA0 = ((const uint4*)(gA + off))[0];
                rA1 = ((const uint4*)(gA + off))[1];
#pragma unroll
                for (int i = 0; i < 4; i++) rB[i] = ((const float4*)(gB + off))[i];
            }

            // ---- compute 32 k-steps ----
#pragma unroll
            for (int kk = 0; kk < 32; kk++) {
                const float* rowA = SA + kk * SAF;
                const float* rowB = SB + kk * SAF;
                float4 a0 = *(const float4*)(rowA + ty * 4);
                float4 a1 = *(const float4*)(rowA + 64 + ty * 4);
                // B pairs loaded pre-packed (consecutive floats = f32x2 pair)
                ulonglong2 b01 = *(const ulonglong2*)(rowB + tx * 4);
                ulonglong2 b23 = *(const ulonglong2*)(rowB + 64 + tx * 4);
                unsigned long long bp[4] = {b01.x, b01.y, b23.x, b23.y};

                float av[8] = {a0.x, a0.y, a0.z, a0.w, a1.x, a1.y, a1.z, a1.w};
#pragma unroll
                for (int ia = 0; ia < 8; ia++) {
                    unsigned long long ap = pk2(av[ia], av[ia]);
#pragma unroll
                    for (int ib = 0; ib < 4; ib++)
                        fma2(acc2[ia][ib], ap, bp[ib]);
                }
            }
        }

        // ---- epilogue: write this unit's partial ----
        float* dst0 = g_z1p + (size_t)slab * RR * NN;
#pragma unroll
        for (int ia = 0; ia < 8; ia++) {
            const int r = bm * 128 + ((ia < 4) ? (ty * 4 + ia) : (64 + ty * 4 + ia - 4));
            float* dr = dst0 + (size_t)r * NN + bn * 128;
#pragma unroll
            for (int ib = 0; ib < 4; ib++) {
                float lo, hi;
                upk2(lo, hi, acc2[ia][ib]);
                const int c = (ib < 2) ? (tx * 4 + ib * 2) : (64 + tx * 4 + (ib - 2) * 2);
                dr[c]     = lo;
                dr[c + 1] = hi;
            }
        }
        // no extra sync needed: next unit's first store is ordered past the
        // last iteration's __syncthreads for both buffers
    }
}

// ---------------- C1: fused slab-reduce + LIF scan -> s1 --------------------
__global__ void scan1(float* __restrict__ out)
{
    int idx = blockIdx.x * blockDim.x + threadIdx.x;   // B*N
    if (idx >= BB * NN) return;
    int b = idx >> 9, n = idx & 511;
    float v = 0.0f;
#pragma unroll
    for (int t = 0; t < TT; t++) {
        float z = 0.0f;
        const size_t base = (size_t)(t * BB + b) * NN + n;
#pragma unroll 8
        for (int k = 0; k < NSLAB; k++) z += g_z1p[(size_t)k * RR * NN + base];
        v = 0.5f * v + z;
        float s = (v >= 1.0f) ? 1.0f : 0.0f;
        v = (v >= 1.0f) ? 0.0f : v;
        out[IN_OFF + (size_t)(b * TT + t) * NN + n] = s;
        g_s1[(t * BB + b) * NN + n] = s;
    }
}

// ---------------- C2: z2 = s1 @ w2^T (512x512x512), tiled fp32 --------------
#define BM 64
#define BN 64
#define BK 16
__global__ void __launch_bounds__(256) z2_gemm(const float* __restrict__ w2)
{
    __shared__ float sA[BK][BM + 4];
    __shared__ float sB[BK][BN + 4];
    int tid = threadIdx.x;
    int bmx = blockIdx.x, bnx = blockIdx.y;
    int lk = tid & 15;
    int lr = tid >> 4;
    int ty = tid >> 4, tx = tid & 15;
    float acc[4][4] = {};

    for (int kt = 0; kt < NN / BK; kt++) {
        int kbase = kt * BK;
#pragma unroll
        for (int it = 0; it < 4; it++) {
            int mm = lr + it * 16;
            sA[lk][mm] = g_s1[(size_t)(bmx * BM + mm) * NN + kbase + lk];
            sB[lk][mm] = w2[(size_t)(bnx * BN + mm) * NN + kbase + lk];
        }
        __syncthreads();
#pragma unroll
        for (int kk = 0; kk < BK; kk++) {
            float4 a4 = *(const float4*)&sA[kk][ty * 4];
            float4 b4 = *(const float4*)&sB[kk][tx * 4];
            float av[4] = {a4.x, a4.y, a4.z, a4.w};
            float bv[4] = {b4.x, b4.y, b4.z, b4.w};
#pragma unroll
            for (int iy = 0; iy < 4; iy++)
#pragma unroll
                for (int ix = 0; ix < 4; ix++)
                    acc[iy][ix] = fmaf(av[iy], bv[ix], acc[iy][ix]);
        }
        __syncthreads();
    }
#pragma unroll
    for (int iy = 0; iy < 4; iy++) {
        int r = bmx * BM + ty * 4 + iy;
#pragma unroll
        for (int ix = 0; ix < 4; ix++)
            g_z2[r * NN + bnx * BN + tx * 4 + ix] = acc[iy][ix];
    }
}

// ---------------- C3: LIF scan on z2 ----------------
__global__ void scan2(float* __restrict__ out)
{
    int idx = blockIdx.x * blockDim.x + threadIdx.x;
    if (idx >= BB * NN) return;
    int b = idx >> 9, n = idx & 511;
    float v = 0.0f, sum = 0.0f;
#pragma unroll
    for (int t = 0; t < TT; t++) {
        float z = g_z2[(t * BB + b) * NN + n];
        v = 0.5f * v + z;
        float s = (v >= 1.0f) ? 1.0f : 0.0f;
        v = (v >= 1.0f) ? 0.0f : v;
        out[HID_OFF + (size_t)(b * TT + t) * NN + n] = s;
        sum += s;
    }
    g_mean[b * NN + n] = sum * 0.25f;
}

// ---------------- C4: readout ----------------
__global__ void out_gemm(const float* __restrict__ wout, float* __restrict__ out)
{
    int idx = blockIdx.x * blockDim.x + threadIdx.x;
    if (idx >= BB * OO) return;
    int b = idx >> 4, o = idx & 15;
    float acc = 0.0f;
    const float* mrow = g_mean + (size_t)b * NN;
    const float* w = wout + (size_t)o * NN;
    for (int k = 0; k < NN; k++) acc = fmaf(mrow[k], w[k], acc);
    out[OUT_OFF + b * OO + o] = acc;
}

// ---------------- launch ----------------
extern "C" void kernel_launch(void* const* d_in, const int* in_sizes, int n_in,
                              void* d_out, int out_size)
{
    const float* x     = (const float*)d_in[0];
    const float* wconv = (const float*)d_in[1];
    const float* w1    = (const float*)d_in[2];
    const float* w2    = (const float*)d_in[3];
    const float* wout  = (const float*)d_in[4];
    float* out = (float*)d_out;

    cudaFuncSetAttribute(z1f2, cudaFuncAttributeMaxDynamicSharedMemorySize, Z1_SMEM);

    conv_lif_kernel<<<128 * 64, 256>>>(x, wconv, out);

    z1f2<<<NCTA, 256, Z1_SMEM>>>(w1);

    scan1<<<(BB * NN + 255) / 256, 256>>>(out);

    z2_gemm<<<dim3(8, 8, 1), 256>>>(w2);

    scan2<<<(BB * NN + 255) / 256, 256>>>(out);
    out_gemm<<<(BB * OO + 255) / 256, 256>>>(wout, out);
}

// round 15
// speedup vs baseline: 1.2983x; 1.2983x over previous
#include <cuda_runtime.h>
#include <cuda_bf16.h>
#include <stdint.h>

// ---------------- problem constants ----------------
#define BB   128
#define CCH  8
#define HH   512
#define WW   32
#define KFLAT 131072
#define TT   4
#define NN   512
#define OO   16
#define RR   512

#define OUT_OFF  ((size_t)0)
#define CONV_OFF ((size_t)2048)
#define IN_OFF   ((size_t)67110912)
#define HID_OFF  ((size_t)67373056)

// ---------------- z1 split-K geometry: 18 slabs (16x7296 + 2x7168) ---------
#define SK 18
#define SLAB_BIG   7296     // = 456*16
#define SLAB_SMALL 7168     // = 448*16

__device__ __forceinline__ int slab_k0(int ks) {
    return (ks <= 16) ? ks * SLAB_BIG : 16 * SLAB_BIG + (ks - 16) * SLAB_SMALL;
}
__device__ __forceinline__ int slab_len(int ks) {
    return (ks < 16) ? SLAB_BIG : SLAB_SMALL;
}

// ---------------- scratch ----------------
__device__ __nv_bfloat16 g_S[(size_t)RR * KFLAT];   // spikes {0,1} bf16, row r=t*BB+b
__device__ float g_z1p[(size_t)SK * RR * NN];       // split-K partials (18MB)
__device__ float g_s1[RR * NN];
__device__ float g_z2[RR * NN];
__device__ float g_mean[BB * NN];

// packed f32x2 helpers (Blackwell baseline PTX; ptxas never auto-fuses)
__device__ __forceinline__ unsigned long long pk2(float lo, float hi) {
    unsigned long long r;
    asm("mov.b64 %0, {%1, %2};" : "=l"(r) : "f"(lo), "f"(hi));
    return r;
}
__device__ __forceinline__ void upk2(float& lo, float& hi, unsigned long long v) {
    asm("mov.b64 {%0, %1}, %2;" : "=f"(lo), "=f"(hi) : "l"(v));
}
__device__ __forceinline__ void fma2(unsigned long long& d, unsigned long long a,
                                     unsigned long long b) {
    asm("fma.rn.f32x2 %0, %1, %2, %0;" : "+l"(d) : "l"(a), "l"(b));
}

// ---------------- kernel A: conv 3x3 SAME + 4-step LIF ----------------
__global__ void __launch_bounds__(256) conv_lif_kernel(const float* __restrict__ x,
                                                       const float* __restrict__ wc,
                                                       float* __restrict__ out)
{
    __shared__ float s_wc[144];
    int tid = threadIdx.x;
    if (tid < 144) s_wc[tid] = wc[tid];
    __syncthreads();

    int j    = tid & 31;
    int isub = tid >> 5;
    int blk  = blockIdx.x;
    int b    = blk >> 6;
    int i    = ((blk & 63) << 3) + isub;

    float xv[2][3][3];
#pragma unroll
    for (int c = 0; c < 2; c++) {
        const float* xb = x + (size_t)(b * 2 + c) * (HH * WW);
#pragma unroll
        for (int di = 0; di < 3; di++) {
            int ii = i + di - 1;
            bool iok = ((unsigned)ii < (unsigned)HH);
#pragma unroll
            for (int dj = 0; dj < 3; dj++) {
                int jj = j + dj - 1;
                bool ok = iok && ((unsigned)jj < (unsigned)WW);
                xv[c][di][dj] = ok ? xb[ii * WW + jj] : 0.0f;
            }
        }
    }

    int pix = i * WW + j;
#pragma unroll
    for (int o = 0; o < CCH; o++) {
        float acc = 0.0f;
#pragma unroll
        for (int c = 0; c < 2; c++)
#pragma unroll
            for (int di = 0; di < 3; di++)
#pragma unroll
                for (int dj = 0; dj < 3; dj++)
                    acc = fmaf(xv[c][di][dj], s_wc[o * 18 + c * 9 + di * 3 + dj], acc);

        float v = 0.0f;
        int kidx = o * (HH * WW) + pix;
#pragma unroll
        for (int t = 0; t < TT; t++) {
            v = 0.5f * v + acc;
            float s = (v >= 1.0f) ? 1.0f : 0.0f;
            v = (v >= 1.0f) ? 0.0f : v;
            out[CONV_OFF + (size_t)((b * TT + t) * CCH + o) * (HH * WW) + pix] = s;
            g_S[(size_t)(t * BB + b) * KFLAT + kidx] = __float2bfloat16(s);
        }
    }
}

// -------- kernel B: z1 = S @ w1^T, fp32 packed f32x2 (R12-verified body) ----
// CTA tile 128x128, 256 threads = 16x16, microtile 8x8, BK=16.
// grid (4,4,18) = 288 CTAs -> 2 CTAs/SM resident, one wave. Deterministic.
#define SAF 136    // float stride

__global__ void __launch_bounds__(256, 2) z1f2(const float* __restrict__ w1)
{
    __shared__ float sA[16][SAF];
    __shared__ float sB[16][SAF];

    const int tid = threadIdx.x;
    const int ty = tid >> 4, tx = tid & 15;
    const int bm = blockIdx.x, bn = blockIdx.y, ks = blockIdx.z;
    const int Kc = slab_len(ks);
    const size_t k0 = (size_t)slab_k0(ks);

    // staging map: row m = tid>>1 (0..127), k-half kh = (tid&1)*8
    const int m  = tid >> 1;
    const int kh = (tid & 1) * 8;

    const __nv_bfloat16* gA = g_S + (size_t)(bm * 128 + m) * KFLAT + k0 + kh;
    const float*         gB = w1  + (size_t)(bn * 128 + m) * KFLAT + k0 + kh;

    unsigned long long acc2[8][4];
#pragma unroll
    for (int a = 0; a < 8; a++)
#pragma unroll
        for (int b = 0; b < 4; b++) acc2[a][b] = 0ULL;

    uint4  rA;           // 8 bf16
    float4 rB0, rB1;     // 8 fp32
    rA  = *(const uint4*)gA;
    rB0 = ((const float4*)gB)[0];
    rB1 = ((const float4*)gB)[1];

    const int nIter = Kc / 16;
    for (int kt = 0; kt < nIter; kt++) {
        // ---- stage to smem (A converted bf16->fp32, both stored transposed) ----
        {
            const __nv_bfloat16* ah = (const __nv_bfloat16*)&rA;
            float fb[8] = {rB0.x, rB0.y, rB0.z, rB0.w, rB1.x, rB1.y, rB1.z, rB1.w};
#pragma unroll
            for (int q = 0; q < 8; q++) {
                sA[kh + q][m] = __bfloat162float(ah[q]);
                sB[kh + q][m] = fb[q];
            }
        }
        __syncthreads();

        // ---- prefetch next slab ----
        if (kt + 1 < nIter) {
            const size_t off = (size_t)(kt + 1) * 16;
            rA  = *(const uint4*)(gA + off);
            rB0 = ((const float4*)(gB + off))[0];
            rB1 = ((const float4*)(gB + off))[1];
        }

        // ---- compute 16 k-steps ----
#pragma unroll
        for (int kk = 0; kk < 16; kk++) {
            float4 a0 = *(const float4*)&sA[kk][ty * 4];
            float4 a1 = *(const float4*)&sA[kk][64 + ty * 4];
            float4 b0 = *(const float4*)&sB[kk][tx * 4];
            float4 b1 = *(const float4*)&sB[kk][64 + tx * 4];

            unsigned long long bp[4];
            bp[0] = pk2(b0.x, b0.y);
            bp[1] = pk2(b0.z, b0.w);
            bp[2] = pk2(b1.x, b1.y);
            bp[3] = pk2(b1.z, b1.w);

            float av[8] = {a0.x, a0.y, a0.z, a0.w, a1.x, a1.y, a1.z, a1.w};
#pragma unroll
            for (int ia = 0; ia < 8; ia++) {
                unsigned long long ap = pk2(av[ia], av[ia]);
#pragma unroll
                for (int ib = 0; ib < 4; ib++)
                    fma2(acc2[ia][ib], ap, bp[ib]);
            }
        }
        __syncthreads();
    }

    // ---- epilogue: unpack + write split-K partials ----
    float* dst0 = g_z1p + (size_t)ks * RR * NN;
#pragma unroll
    for (int ia = 0; ia < 8; ia++) {
        const int r = bm * 128 + ((ia < 4) ? (ty * 4 + ia) : (64 + ty * 4 + ia - 4));
        float* dr = dst0 + (size_t)r * NN + bn * 128;
#pragma unroll
        for (int ib = 0; ib < 4; ib++) {
            float lo, hi;
            upk2(lo, hi, acc2[ia][ib]);
            const int c = (ib < 2) ? (tx * 4 + ib * 2) : (64 + tx * 4 + (ib - 2) * 2);
            dr[c]     = lo;
            dr[c + 1] = hi;
        }
    }
}

// ---------------- C1: fused split-K reduce + LIF scan -> s1 -----------------
__global__ void scan1(float* __restrict__ out)
{
    int idx = blockIdx.x * blockDim.x + threadIdx.x;   // B*N
    if (idx >= BB * NN) return;
    int b = idx >> 9, n = idx & 511;
    float v = 0.0f;
#pragma unroll
    for (int t = 0; t < TT; t++) {
        float z = 0.0f;
        const size_t base = (size_t)(t * BB + b) * NN + n;
#pragma unroll
        for (int k = 0; k < SK; k++) z += g_z1p[(size_t)k * RR * NN + base];
        v = 0.5f * v + z;
        float s = (v >= 1.0f) ? 1.0f : 0.0f;
        v = (v >= 1.0f) ? 0.0f : v;
        out[IN_OFF + (size_t)(b * TT + t) * NN + n] = s;
        g_s1[(t * BB + b) * NN + n] = s;
    }
}

// ---------------- C2: z2 = s1 @ w2^T (512x512x512), tiled fp32 --------------
#define BM 64
#define BN 64
#define BK 16
__global__ void __launch_bounds__(256) z2_gemm(const float* __restrict__ w2)
{
    __shared__ float sA[BK][BM + 4];
    __shared__ float sB[BK][BN + 4];
    int tid = threadIdx.x;
    int bmx = blockIdx.x, bnx = blockIdx.y;
    int lk = tid & 15;
    int lr = tid >> 4;
    int ty = tid >> 4, tx = tid & 15;
    float acc[4][4] = {};

    for (int kt = 0; kt < NN / BK; kt++) {
        int kbase = kt * BK;
#pragma unroll
        for (int it = 0; it < 4; it++) {
            int mm = lr + it * 16;
            sA[lk][mm] = g_s1[(size_t)(bmx * BM + mm) * NN + kbase + lk];
            sB[lk][mm] = w2[(size_t)(bnx * BN + mm) * NN + kbase + lk];
        }
        __syncthreads();
#pragma unroll
        for (int kk = 0; kk < BK; kk++) {
            float4 a4 = *(const float4*)&sA[kk][ty * 4];
            float4 b4 = *(const float4*)&sB[kk][tx * 4];
            float av[4] = {a4.x, a4.y, a4.z, a4.w};
            float bv[4] = {b4.x, b4.y, b4.z, b4.w};
#pragma unroll
            for (int iy = 0; iy < 4; iy++)
#pragma unroll
                for (int ix = 0; ix < 4; ix++)
                    acc[iy][ix] = fmaf(av[iy], bv[ix], acc[iy][ix]);
        }
        __syncthreads();
    }
#pragma unroll
    for (int iy = 0; iy < 4; iy++) {
        int r = bmx * BM + ty * 4 + iy;
#pragma unroll
        for (int ix = 0; ix < 4; ix++)
            g_z2[r * NN + bnx * BN + tx * 4 + ix] = acc[iy][ix];
    }
}

// ---------------- C3: LIF scan on z2 ----------------
__global__ void scan2(float* __restrict__ out)
{
    int idx = blockIdx.x * blockDim.x + threadIdx.x;
    if (idx >= BB * NN) return;
    int b = idx >> 9, n = idx & 511;
    float v = 0.0f, sum = 0.0f;
#pragma unroll
    for (int t = 0; t < TT; t++) {
        float z = g_z2[(t * BB + b) * NN + n];
        v = 0.5f * v + z;
        float s = (v >= 1.0f) ? 1.0f : 0.0f;
        v = (v >= 1.0f) ? 0.0f : v;
        out[HID_OFF + (size_t)(b * TT + t) * NN + n] = s;
        sum += s;
    }
    g_mean[b * NN + n] = sum * 0.25f;
}

// ---------------- C4: readout ----------------
__global__ void out_gemm(const float* __restrict__ wout, float* __restrict__ out)
{
    int idx = blockIdx.x * blockDim.x + threadIdx.x;
    if (idx >= BB * OO) return;
    int b = idx >> 4, o = idx & 15;
    float acc = 0.0f;
    const float* mrow = g_mean + (size_t)b * NN;
    const float* w = wout + (size_t)o * NN;
    for (int k = 0; k < NN; k++) acc = fmaf(mrow[k], w[k], acc);
    out[OUT_OFF + b * OO + o] = acc;
}

// ---------------- launch ----------------
extern "C" void kernel_launch(void* const* d_in, const int* in_sizes, int n_in,
                              void* d_out, int out_size)
{
    const float* x     = (const float*)d_in[0];
    const float* wconv = (const float*)d_in[1];
    const float* w1    = (const float*)d_in[2];
    const float* w2    = (const float*)d_in[3];
    const float* wout  = (const float*)d_in[4];
    float* out = (float*)d_out;

    conv_lif_kernel<<<128 * 64, 256>>>(x, wconv, out);

    z1f2<<<dim3(4, 4, SK), 256>>>(w1);

    scan1<<<(BB * NN + 255) / 256, 256>>>(out);

    z2_gemm<<<dim3(8, 8, 1), 256>>>(w2);

    scan2<<<(BB * NN + 255) / 256, 256>>>(out);
    out_gemm<<<(BB * OO + 255) / 256, 256>>>(wout, out);
}

// round 17
// speedup vs baseline: 1.3445x; 1.0356x over previous
#include <cuda_runtime.h>
#include <cuda_bf16.h>
#include <stdint.h>

// ---------------- problem constants ----------------
#define BB   128
#define CCH  8
#define HH   512
#define WW   32
#define HW   (HH * WW)
#define KFLAT 131072
#define TT   4
#define NN   512
#define OO   16
#define RR   512

#define OUT_OFF  ((size_t)0)
#define CONV_OFF ((size_t)2048)
#define IN_OFF   ((size_t)67110912)
#define HID_OFF  ((size_t)67373056)

// ---------------- z1 split-K geometry: 18 slabs (16x7296 + 2x7168) ---------
#define SK 18
#define SLAB_BIG   7296
#define SLAB_SMALL 7168

__device__ __forceinline__ int slab_k0(int ks) {
    return (ks <= 16) ? ks * SLAB_BIG : 16 * SLAB_BIG + (ks - 16) * SLAB_SMALL;
}
__device__ __forceinline__ int slab_len(int ks) {
    return (ks < 16) ? SLAB_BIG : SLAB_SMALL;
}

// ---------------- scratch ----------------
__device__ __nv_bfloat16 g_S[(size_t)RR * KFLAT];   // spikes {0,1} bf16, row r=t*BB+b
__device__ float g_z1p[(size_t)SK * RR * NN];       // z1 split-K partials
#define ZSK 4
__device__ float g_z2p[(size_t)ZSK * RR * NN];      // z2 split-K partials
__device__ float g_s1[RR * NN];
__device__ float g_mean[BB * NN];

// packed f32x2 helpers
__device__ __forceinline__ unsigned long long pk2(float lo, float hi) {
    unsigned long long r;
    asm("mov.b64 %0, {%1, %2};" : "=l"(r) : "f"(lo), "f"(hi));
    return r;
}
__device__ __forceinline__ void upk2(float& lo, float& hi, unsigned long long v) {
    asm("mov.b64 {%0, %1}, %2;" : "=f"(lo), "=f"(hi) : "l"(v));
}
__device__ __forceinline__ void fma2(unsigned long long& d, unsigned long long a,
                                     unsigned long long b) {
    asm("fma.rn.f32x2 %0, %1, %2, %0;" : "+l"(d) : "l"(a), "l"(b));
}

// ---------------- kernel A: conv 3x3 SAME + 4-step LIF, vectorized stores ---
// 2048 blocks (b x 16 row-chunks), 256 threads = (32 rows x 8 col-groups of 4)
__global__ void __launch_bounds__(256) conv_lif_kernel(const float* __restrict__ x,
                                                       const float* __restrict__ wc,
                                                       float* __restrict__ out)
{
    __shared__ float s_wc[144];
    int tid = threadIdx.x;
    if (tid < 144) s_wc[tid] = wc[tid];
    __syncthreads();

    const int jg   = tid & 7;
    const int isub = tid >> 3;             // 0..31
    const int j4   = jg * 4;
    const int b  = blockIdx.x >> 4;
    const int i  = ((blockIdx.x & 15) << 5) + isub;

    // neighborhood: 2ch x 3 rows x 6 cols (covers j4-1 .. j4+4)
    float xv[2][3][6];
#pragma unroll
    for (int c = 0; c < 2; c++) {
        const float* xb = x + (size_t)(b * 2 + c) * HW;
#pragma unroll
        for (int di = 0; di < 3; di++) {
            int ii = i + di - 1;
            bool iok = ((unsigned)ii < (unsigned)HH);
#pragma unroll
            for (int d6 = 0; d6 < 6; d6++) {
                int jj = j4 + d6 - 1;
                bool ok = iok && ((unsigned)jj < (unsigned)WW);
                xv[c][di][d6] = ok ? xb[ii * WW + jj] : 0.0f;
            }
        }
    }

    const int pix = i * WW + j4;
#pragma unroll
    for (int o = 0; o < CCH; o++) {
        float a4[4] = {0.0f, 0.0f, 0.0f, 0.0f};
#pragma unroll
        for (int c = 0; c < 2; c++)
#pragma unroll
            for (int di = 0; di < 3; di++)
#pragma unroll
                for (int dd = 0; dd < 3; dd++) {
                    float w = s_wc[o * 18 + c * 9 + di * 3 + dd];
#pragma unroll
                    for (int q = 0; q < 4; q++)
                        a4[q] = fmaf(xv[c][di][q + dd], w, a4[q]);
                }

        float v[4] = {0.0f, 0.0f, 0.0f, 0.0f};
        const int kbase = o * HW + pix;
#pragma unroll
        for (int t = 0; t < TT; t++) {
            float4 sp;
            __nv_bfloat16 hb[4];
            float* s4 = &sp.x;
#pragma unroll
            for (int q = 0; q < 4; q++) {
                v[q] = 0.5f * v[q] + a4[q];
                float s = (v[q] >= 1.0f) ? 1.0f : 0.0f;
                v[q] = (v[q] >= 1.0f) ? 0.0f : v[q];
                s4[q] = s;
                hb[q] = __float2bfloat16(s);
            }
            *(float4*)&out[CONV_OFF + (size_t)((b * TT + t) * CCH + o) * HW + pix] = sp;
            *(uint2*)&g_S[(size_t)(t * BB + b) * KFLAT + kbase] = *(uint2*)hb;
        }
    }
}

// -------- kernel B: z1 = S @ w1^T, f32x2, double-buffered smem --------------
// CTA tile 128x128, 256 threads = 16x16, microtile 8x8, BK=16, 2 smem stages,
// ONE __syncthreads per iteration. grid (4,4,18), 2 CTAs/SM. Deterministic.
#define SAF 136

__global__ void __launch_bounds__(256, 2) z1f2(const float* __restrict__ w1)
{
    __shared__ float sA[2][16][SAF];
    __shared__ float sB[2][16][SAF];

    const int tid = threadIdx.x;
    const int ty = tid >> 4, tx = tid & 15;
    const int bm = blockIdx.x, bn = blockIdx.y, ks = blockIdx.z;
    const int Kc = slab_len(ks);
    const size_t k0 = (size_t)slab_k0(ks);

    const int m  = tid >> 1;
    const int kh = (tid & 1) * 8;

    const __nv_bfloat16* gA = g_S + (size_t)(bm * 128 + m) * KFLAT + k0 + kh;
    const float*         gB = w1  + (size_t)(bn * 128 + m) * KFLAT + k0 + kh;

    unsigned long long acc2[8][4];
#pragma unroll
    for (int a = 0; a < 8; a++)
#pragma unroll
        for (int b = 0; b < 4; b++) acc2[a][b] = 0ULL;

    uint4  rA;
    float4 rB0, rB1;

    // preload tile 0 into stage 0
    rA  = *(const uint4*)gA;
    rB0 = ((const float4*)gB)[0];
    rB1 = ((const float4*)gB)[1];
    {
        const __nv_bfloat16* ah = (const __nv_bfloat16*)&rA;
        float fb[8] = {rB0.x, rB0.y, rB0.z, rB0.w, rB1.x, rB1.y, rB1.z, rB1.w};
#pragma unroll
        for (int q = 0; q < 8; q++) {
            sA[0][kh + q][m] = __bfloat162float(ah[q]);
            sB[0][kh + q][m] = fb[q];
        }
    }
    __syncthreads();

    const int nIter = Kc / 16;
    for (int kt = 0; kt < nIter; kt++) {
        const int cur = kt & 1;
        const bool more = (kt + 1) < nIter;

        // ---- prefetch next slab to regs (issue before compute) ----
        if (more) {
            const size_t off = (size_t)(kt + 1) * 16;
            rA  = *(const uint4*)(gA + off);
            rB0 = ((const float4*)(gB + off))[0];
            rB1 = ((const float4*)(gB + off))[1];
        }

        // ---- compute 16 k-steps on stage cur ----
#pragma unroll
        for (int kk = 0; kk < 16; kk++) {
            float4 a0 = *(const float4*)&sA[cur][kk][ty * 4];
            float4 a1 = *(const float4*)&sA[cur][kk][64 + ty * 4];
            float4 b0 = *(const float4*)&sB[cur][kk][tx * 4];
            float4 b1 = *(const float4*)&sB[cur][kk][64 + tx * 4];

            unsigned long long bp[4];
            bp[0] = pk2(b0.x, b0.y);
            bp[1] = pk2(b0.z, b0.w);
            bp[2] = pk2(b1.x, b1.y);
            bp[3] = pk2(b1.z, b1.w);

            float av[8] = {a0.x, a0.y, a0.z, a0.w, a1.x, a1.y, a1.z, a1.w};
#pragma unroll
            for (int ia = 0; ia < 8; ia++) {
                unsigned long long ap = pk2(av[ia], av[ia]);
#pragma unroll
                for (int ib = 0; ib < 4; ib++)
                    fma2(acc2[ia][ib], ap, bp[ib]);
            }
        }

        // ---- store prefetched tile into the other stage ----
        if (more) {
            const int nxt = cur ^ 1;
            const __nv_bfloat16* ah = (const __nv_bfloat16*)&rA;
            float fb[8] = {rB0.x, rB0.y, rB0.z, rB0.w, rB1.x, rB1.y, rB1.z, rB1.w};
#pragma unroll
            for (int q = 0; q < 8; q++) {
                sA[nxt][kh + q][m] = __bfloat162float(ah[q]);
                sB[nxt][kh + q][m] = fb[q];
            }
        }
        __syncthreads();
    }

    // ---- epilogue ----
    float* dst0 = g_z1p + (size_t)ks * RR * NN;
#pragma unroll
    for (int ia = 0; ia < 8; ia++) {
        const int r = bm * 128 + ((ia < 4) ? (ty * 4 + ia) : (64 + ty * 4 + ia - 4));
        float* dr = dst0 + (size_t)r * NN + bn * 128;
#pragma unroll
        for (int ib = 0; ib < 4; ib++) {
            float lo, hi;
            upk2(lo, hi, acc2[ia][ib]);
            const int c = (ib < 2) ? (tx * 4 + ib * 2) : (64 + tx * 4 + (ib - 2) * 2);
            dr[c]     = lo;
            dr[c + 1] = hi;
        }
    }
}

// ---------------- C1: fused split-K reduce + LIF scan -> s1 -----------------
__global__ void scan1(float* __restrict__ out)
{
    int idx = blockIdx.x * blockDim.x + threadIdx.x;
    if (idx >= BB * NN) return;
    int b = idx >> 9, n = idx & 511;
    float v = 0.0f;
#pragma unroll
    for (int t = 0; t < TT; t++) {
        float z = 0.0f;
        const size_t base = (size_t)(t * BB + b) * NN + n;
#pragma unroll
        for (int k = 0; k < SK; k++) z += g_z1p[(size_t)k * RR * NN + base];
        v = 0.5f * v + z;
        float s = (v >= 1.0f) ? 1.0f : 0.0f;
        v = (v >= 1.0f) ? 0.0f : v;
        out[IN_OFF + (size_t)(b * TT + t) * NN + n] = s;
        g_s1[(t * BB + b) * NN + n] = s;
    }
}

// ---------------- C2: z2 = s1 @ w2^T, split-K x4 ----------------------------
#define BM 64
#define BN 64
#define BK 16
__global__ void __launch_bounds__(256) z2_gemm(const float* __restrict__ w2)
{
    __shared__ float sA[BK][BM + 4];
    __shared__ float sB[BK][BN + 4];
    int tid = threadIdx.x;
    int bmx = blockIdx.x, bnx = blockIdx.y, ks = blockIdx.z;
    int lk = tid & 15;
    int lr = tid >> 4;
    int ty = tid >> 4, tx = tid & 15;
    float acc[4][4] = {};

    const int kbeg = ks * (NN / ZSK);      // 128-wide K ranges
    for (int kt = 0; kt < (NN / ZSK) / BK; kt++) {
        int kbase = kbeg + kt * BK;
#pragma unroll
        for (int it = 0; it < 4; it++) {
            int mm = lr + it * 16;
            sA[lk][mm] = g_s1[(size_t)(bmx * BM + mm) * NN + kbase + lk];
            sB[lk][mm] = w2[(size_t)(bnx * BN + mm) * NN + kbase + lk];
        }
        __syncthreads();
#pragma unroll
        for (int kk = 0; kk < BK; kk++) {
            float4 a4 = *(const float4*)&sA[kk][ty * 4];
            float4 b4 = *(const float4*)&sB[kk][tx * 4];
            float av[4] = {a4.x, a4.y, a4.z, a4.w};
            float bv[4] = {b4.x, b4.y, b4.z, b4.w};
#pragma unroll
            for (int iy = 0; iy < 4; iy++)
#pragma unroll
                for (int ix = 0; ix < 4; ix++)
                    acc[iy][ix] = fmaf(av[iy], bv[ix], acc[iy][ix]);
        }
        __syncthreads();
    }
    float* dst = g_z2p + (size_t)ks * RR * NN;
#pragma unroll
    for (int iy = 0; iy < 4; iy++) {
        int r = bmx * BM + ty * 4 + iy;
#pragma unroll
        for (int ix = 0; ix < 4; ix++)
            dst[(size_t)r * NN + bnx * BN + tx * 4 + ix] = acc[iy][ix];
    }
}

// ---------------- C3: fused z2-reduce + LIF scan ----------------------------
__global__ void scan2(float* __restrict__ out)
{
    int idx = blockIdx.x * blockDim.x + threadIdx.x;
    if (idx >= BB * NN) return;
    int b = idx >> 9, n = idx & 511;
    float v = 0.0f, sum = 0.0f;
#pragma unroll
    for (int t = 0; t < TT; t++) {
        const size_t base = (size_t)(t * BB + b) * NN + n;
        float z = 0.0f;
#pragma unroll
        for (int k = 0; k < ZSK; k++) z += g_z2p[(size_t)k * RR * NN + base];
        v = 0.5f * v + z;
        float s = (v >= 1.0f) ? 1.0f : 0.0f;
        v = (v >= 1.0f) ? 0.0f : v;
        out[HID_OFF + (size_t)(b * TT + t) * NN + n] = s;
        sum += s;
    }
    g_mean[b * NN + n] = sum * 0.25f;
}

// ---------------- C4: readout ----------------
__global__ void out_gemm(const float* __restrict__ wout, float* __restrict__ out)
{
    int idx = blockIdx.x * blockDim.x + threadIdx.x;
    if (idx >= BB * OO) return;
    int b = idx >> 4, o = idx & 15;
    float acc = 0.0f;
    const float* mrow = g_mean + (size_t)b * NN;
    const float* w = wout + (size_t)o * NN;
    for (int k = 0; k < NN; k++) acc = fmaf(mrow[k], w[k], acc);
    out[OUT_OFF + b * OO + o] = acc;
}

// ---------------- launch ----------------
extern "C" void kernel_launch(void* const* d_in, const int* in_sizes, int n_in,
                              void* d_out, int out_size)
{
    const float* x     = (const float*)d_in[0];
    const float* wconv = (const float*)d_in[1];
    const float* w1    = (const float*)d_in[2];
    const float* w2    = (const float*)d_in[3];
    const float* wout  = (const float*)d_in[4];
    float* out = (float*)d_out;

    conv_lif_kernel<<<128 * 16, 256>>>(x, wconv, out);

    z1f2<<<dim3(4, 4, SK), 256>>>(w1);

    scan1<<<(BB * NN + 255) / 256, 256>>>(out);

    z2_gemm<<<dim3(8, 8, ZSK), 256>>>(w2);

    scan2<<<(BB * NN + 255) / 256, 256>>>(out);
    out_gemm<<<(BB * OO + 255) / 256, 256>>>(wout, out);
}